// round 11
// baseline (speedup 1.0000x reference)
#include <cuda_runtime.h>

// Problem constants
#define Bn 8
#define Tn 2048
#define Cn 1024
#define Hn 64
#define Mn (Bn * Tn)   // 16384 rows

// Scratch for Q, K, V projections (device globals: no runtime allocation)
__device__ float g_Q[(size_t)Mn * Hn];
__device__ float g_K[(size_t)Mn * Hn];
__device__ float g_V[(size_t)Mn * Hn];

// ---------------------------------------------------------------------------
// Kernel 1: fused QKV projection.
// out[m, 0:64] = (x @ Wq) * 0.125   (1/sqrt(H) folded into Q)
// out[m,64:128] = x @ Wk
// out[m,128:192] = x @ Wv
// Tiling: BM=64 rows, BN=192 cols (all three heads), KC=32.
// 256 threads, each computes a 4x12 register tile.
// ---------------------------------------------------------------------------
__global__ __launch_bounds__(256, 2)
void qkv_kernel(const float* __restrict__ x,
                const float* __restrict__ Wq,
                const float* __restrict__ Wk,
                const float* __restrict__ Wv)
{
    constexpr int KC = 32;
    __shared__ __align__(16) float As[KC][64];    // x tile, transposed [k][m]
    __shared__ __align__(16) float Bs[KC][192];   // W tile [k][n]  (n: 0..63 Q, 64..127 K, 128..191 V)

    const int t  = threadIdx.x;
    const int ty = t >> 4;        // 0..15 -> 4 rows each
    const int tx = t & 15;        // 0..15 -> 12 cols each
    const int m0 = blockIdx.x * 64;

    const int mm = t & 63;        // row handled by this thread for A-load
    const int cq = t >> 6;        // 0..3  -> 8 k-dims each

    float acc[4][12];
#pragma unroll
    for (int i = 0; i < 4; ++i)
#pragma unroll
        for (int j = 0; j < 12; ++j) acc[i][j] = 0.f;

    for (int kt = 0; kt < Cn; kt += KC) {
        // ---- load x tile (transposed store: conflict-free, bank = mm%32) ----
#pragma unroll
        for (int u = 0; u < 2; ++u) {
            float4 v = *reinterpret_cast<const float4*>(
                &x[(size_t)(m0 + mm) * Cn + kt + cq * 8 + u * 4]);
            int d = cq * 8 + u * 4;
            As[d + 0][mm] = v.x;
            As[d + 1][mm] = v.y;
            As[d + 2][mm] = v.z;
            As[d + 3][mm] = v.w;
        }
        // ---- load W tile: 32 x 192 floats = 1536 float4, 6 per thread ----
#pragma unroll
        for (int r = 0; r < 6; ++r) {
            int f  = t + 256 * r;     // 0..1535
            int k  = f / 48;          // 0..31
            int nq = f % 48;          // 0..47 (each = 4 cols)
            int w  = nq >> 4;         // 0,1,2 -> Wq,Wk,Wv
            int nc = (nq & 15) * 4;   // 0..60
            const float* W = (w == 0) ? Wq : (w == 1) ? Wk : Wv;
            float4 v = *reinterpret_cast<const float4*>(&W[(size_t)(kt + k) * Hn + nc]);
            *reinterpret_cast<float4*>(&Bs[k][w * 64 + nc]) = v;
        }
        __syncthreads();

#pragma unroll 8
        for (int k = 0; k < KC; ++k) {
            float4 a  = *reinterpret_cast<const float4*>(&As[k][ty * 4]);
            float4 b0 = *reinterpret_cast<const float4*>(&Bs[k][tx * 12]);
            float4 b1 = *reinterpret_cast<const float4*>(&Bs[k][tx * 12 + 4]);
            float4 b2 = *reinterpret_cast<const float4*>(&Bs[k][tx * 12 + 8]);
            float av[4]  = {a.x, a.y, a.z, a.w};
            float bv[12] = {b0.x, b0.y, b0.z, b0.w,
                            b1.x, b1.y, b1.z, b1.w,
                            b2.x, b2.y, b2.z, b2.w};
#pragma unroll
            for (int i = 0; i < 4; ++i)
#pragma unroll
                for (int j = 0; j < 12; ++j)
                    acc[i][j] = fmaf(av[i], bv[j], acc[i][j]);
        }
        __syncthreads();
    }

    // ---- epilogue: scatter to Q (scaled), K, V ----
#pragma unroll
    for (int i = 0; i < 4; ++i) {
        const size_t m = (size_t)(m0 + ty * 4 + i);
#pragma unroll
        for (int j = 0; j < 12; ++j) {
            int n   = tx * 12 + j;
            float v = acc[i][j];
            if (n < 64)       g_Q[m * Hn + n]         = v * 0.125f;
            else if (n < 128) g_K[m * Hn + (n - 64)]  = v;
            else              g_V[m * Hn + (n - 128)] = v;
        }
    }
}

// ---------------------------------------------------------------------------
// Kernel 2: causal flash attention (fp32, online softmax).
// One CTA per (batch, 64-query tile). 256 threads as 16x16:
//   ty -> 4 query rows each, tx -> 4 key-cols (for S) / 4 head-dims (for O).
// SMEM: Qs[dim][row], KP[...] (K transposed, then reused for P), Vs[key][dim].
// Static SMEM = 3 * 16KB = 48KB exactly.
// Heavy (large-qt) tiles launched first for wave balance.
// ---------------------------------------------------------------------------
__global__ __launch_bounds__(256, 2)
void attn_kernel(float* __restrict__ out)
{
    __shared__ __align__(16) float Qs[64][64];  // [dim][row]
    __shared__ __align__(16) float KP[64][64];  // K as [dim][key]; later P as [row][key]
    __shared__ __align__(16) float Vs[64][64];  // [key][dim]

    const int t  = threadIdx.x;
    const int ty = t >> 4;                 // 0..15
    const int tx = t & 15;                 // 0..15
    const int qt = 31 - (int)(blockIdx.x >> 3);  // descending: heavy tiles first
    const int b  = blockIdx.x & 7;
    const int q0 = qt * 64;

    // ---- load Q tile transposed ----
    {
        const int rr = t & 63;             // row (query) index
        const int dq = t >> 6;             // 0..3 -> 16 dims each
        const float* Qg = g_Q + (size_t)(b * Tn + q0) * Hn;
#pragma unroll
        for (int u = 0; u < 4; ++u) {
            float4 v = *reinterpret_cast<const float4*>(&Qg[(size_t)rr * Hn + dq * 16 + u * 4]);
            int d = dq * 16 + u * 4;
            Qs[d + 0][rr] = v.x;
            Qs[d + 1][rr] = v.y;
            Qs[d + 2][rr] = v.z;
            Qs[d + 3][rr] = v.w;
        }
    }

    float m[4], l[4], O[4][4];
#pragma unroll
    for (int i = 0; i < 4; ++i) {
        m[i] = -1e30f;
        l[i] = 0.f;
#pragma unroll
        for (int j = 0; j < 4; ++j) O[i][j] = 0.f;
    }

    for (int jt = 0; jt <= qt; ++jt) {
        const int j0 = jt * 64;

        // ---- load K tile (transposed) + V tile (natural) ----
        {
            const int rr = t & 63, dq = t >> 6;
            const float* Kg = g_K + (size_t)(b * Tn + j0) * Hn;
#pragma unroll
            for (int u = 0; u < 4; ++u) {
                float4 v = *reinterpret_cast<const float4*>(&Kg[(size_t)rr * Hn + dq * 16 + u * 4]);
                int d = dq * 16 + u * 4;
                KP[d + 0][rr] = v.x;
                KP[d + 1][rr] = v.y;
                KP[d + 2][rr] = v.z;
                KP[d + 3][rr] = v.w;
            }
            const int kk = t >> 2, seg = t & 3;
            const float* Vg = g_V + (size_t)(b * Tn + j0) * Hn;
#pragma unroll
            for (int u = 0; u < 4; ++u) {
                *reinterpret_cast<float4*>(&Vs[kk][seg * 16 + u * 4]) =
                    *reinterpret_cast<const float4*>(&Vg[(size_t)kk * Hn + seg * 16 + u * 4]);
            }
        }
        __syncthreads();

        // ---- S = Q @ K^T (4x4 per thread) ----
        float s[4][4];
#pragma unroll
        for (int i = 0; i < 4; ++i)
#pragma unroll
            for (int j = 0; j < 4; ++j) s[i][j] = 0.f;

#pragma unroll 16
        for (int k = 0; k < 64; ++k) {
            float4 qv = *reinterpret_cast<const float4*>(&Qs[k][ty * 4]);
            float4 kv = *reinterpret_cast<const float4*>(&KP[k][tx * 4]);
            float qa[4] = {qv.x, qv.y, qv.z, qv.w};
            float kb[4] = {kv.x, kv.y, kv.z, kv.w};
#pragma unroll
            for (int i = 0; i < 4; ++i)
#pragma unroll
                for (int j = 0; j < 4; ++j)
                    s[i][j] = fmaf(qa[i], kb[j], s[i][j]);
        }

        // ---- causal mask (only diagonal tile) ----
        if (jt == qt) {
#pragma unroll
            for (int i = 0; i < 4; ++i)
#pragma unroll
                for (int j = 0; j < 4; ++j)
                    if (tx * 4 + j > ty * 4 + i) s[i][j] = -1e30f;
        }

        // ---- online softmax update ----
#pragma unroll
        for (int i = 0; i < 4; ++i) {
            float rmax = fmaxf(fmaxf(s[i][0], s[i][1]), fmaxf(s[i][2], s[i][3]));
#pragma unroll
            for (int off = 8; off; off >>= 1)
                rmax = fmaxf(rmax, __shfl_xor_sync(0xffffffffu, rmax, off, 16));
            float mnew = fmaxf(m[i], rmax);
            float f    = __expf(m[i] - mnew);
            m[i] = mnew;
            float rsum = 0.f;
#pragma unroll
            for (int j = 0; j < 4; ++j) {
                float p = __expf(s[i][j] - mnew);
                s[i][j] = p;
                rsum += p;
            }
            l[i] = l[i] * f + rsum;     // per-thread partial l (reduced at end)
#pragma unroll
            for (int j = 0; j < 4; ++j) O[i][j] *= f;
        }

        __syncthreads();   // everyone done reading KP as K

        // ---- store P into KP as [row][key] ----
#pragma unroll
        for (int i = 0; i < 4; ++i)
#pragma unroll
            for (int j = 0; j < 4; ++j)
                KP[ty * 4 + i][tx * 4 + j] = s[i][j];
        __syncthreads();

        // ---- O += P @ V ----
#pragma unroll 16
        for (int k = 0; k < 64; ++k) {
            float4 v4 = *reinterpret_cast<const float4*>(&Vs[k][tx * 4]);
            float p0 = KP[ty * 4 + 0][k];
            float p1 = KP[ty * 4 + 1][k];
            float p2 = KP[ty * 4 + 2][k];
            float p3 = KP[ty * 4 + 3][k];
            O[0][0] = fmaf(p0, v4.x, O[0][0]); O[0][1] = fmaf(p0, v4.y, O[0][1]);
            O[0][2] = fmaf(p0, v4.z, O[0][2]); O[0][3] = fmaf(p0, v4.w, O[0][3]);
            O[1][0] = fmaf(p1, v4.x, O[1][0]); O[1][1] = fmaf(p1, v4.y, O[1][1]);
            O[1][2] = fmaf(p1, v4.z, O[1][2]); O[1][3] = fmaf(p1, v4.w, O[1][3]);
            O[2][0] = fmaf(p2, v4.x, O[2][0]); O[2][1] = fmaf(p2, v4.y, O[2][1]);
            O[2][2] = fmaf(p2, v4.z, O[2][2]); O[2][3] = fmaf(p2, v4.w, O[2][3]);
            O[3][0] = fmaf(p3, v4.x, O[3][0]); O[3][1] = fmaf(p3, v4.y, O[3][1]);
            O[3][2] = fmaf(p3, v4.z, O[3][2]); O[3][3] = fmaf(p3, v4.w, O[3][3]);
        }
        __syncthreads();   // before next tile overwrites KP/Vs
    }

    // ---- finalize: reduce l across the 16 col-threads, normalize, write ----
#pragma unroll
    for (int i = 0; i < 4; ++i) {
#pragma unroll
        for (int off = 8; off; off >>= 1)
            l[i] += __shfl_xor_sync(0xffffffffu, l[i], off, 16);
        float inv = 1.f / l[i];
        size_t q  = (size_t)(b * Tn) + q0 + ty * 4 + i;
        float4 o4 = make_float4(O[i][0] * inv, O[i][1] * inv,
                                O[i][2] * inv, O[i][3] * inv);
        *reinterpret_cast<float4*>(&out[q * Hn + tx * 4]) = o4;
    }
}

// ---------------------------------------------------------------------------
extern "C" void kernel_launch(void* const* d_in, const int* in_sizes, int n_in,
                              void* d_out, int out_size)
{
    (void)in_sizes; (void)n_in; (void)out_size;
    const float* x  = (const float*)d_in[0];
    const float* Wq = (const float*)d_in[1];
    const float* Wk = (const float*)d_in[2];
    const float* Wv = (const float*)d_in[3];
    float* out = (float*)d_out;

    qkv_kernel<<<Mn / 64, 256>>>(x, Wq, Wk, Wv);
    attn_kernel<<<Bn * (Tn / 64), 256>>>(out);
}

// round 12
// speedup vs baseline: 1.0485x; 1.0485x over previous
#include <cuda_runtime.h>

// Problem constants
#define Bn 8
#define Tn 2048
#define Cn 1024
#define Hn 64
#define Mn (Bn * Tn)   // 16384 rows

// Scratch for Q, K, V projections (device globals: no runtime allocation)
__device__ float g_Q[(size_t)Mn * Hn];
__device__ float g_K[(size_t)Mn * Hn];
__device__ float g_V[(size_t)Mn * Hn];

// ---------------------------------------------------------------------------
// Helpers
// ---------------------------------------------------------------------------
__device__ __forceinline__ float f2tf(float f) {
    unsigned u;
    asm("cvt.rna.tf32.f32 %0, %1;" : "=r"(u) : "f"(f));
    return __uint_as_float(u);
}

__device__ __forceinline__ void mma_tf32(float& d0, float& d1, float& d2, float& d3,
                                         unsigned a0, unsigned a1, unsigned a2, unsigned a3,
                                         unsigned b0, unsigned b1)
{
    asm volatile(
        "mma.sync.aligned.m16n8k8.row.col.f32.tf32.tf32.f32 "
        "{%0,%1,%2,%3}, {%4,%5,%6,%7}, {%8,%9}, {%0,%1,%2,%3};\n"
        : "+f"(d0), "+f"(d1), "+f"(d2), "+f"(d3)
        : "r"(a0), "r"(a1), "r"(a2), "r"(a3), "r"(b0), "r"(b1));
}

// k16-chunk swizzled smem index: tile row `row`, k = c4 + 4*k4 within chunk.
// Layout row*16 + ((c4 ^ (row&3))<<2) + k4  -> LDS.128 at (row, c4) is
// conflict-free across the 8-thread phases of a warp fragment load.
__device__ __forceinline__ int swz(int row, int c4, int k4) {
    return row * 16 + (((c4 ^ (row & 3))) << 2) + k4;
}

// ---------------------------------------------------------------------------
// Kernel 1: fused QKV projection via tf32 mma.
// C[16384 x 192] = x[16384 x 1024] @ [Wq|Wk|Wv], Q scaled by 1/8.
// BM=64, BN=192, BK=16, 256 threads = 8 warps as 2(m) x 4(n), warp tile 32x48.
// Double-buffered smem, tf32 conversion at STS.
// ---------------------------------------------------------------------------
__global__ __launch_bounds__(256, 2)
void qkv_mma(const float* __restrict__ x, const float* __restrict__ Wq,
             const float* __restrict__ Wk, const float* __restrict__ Wv)
{
    __shared__ __align__(16) float As[2][64 * 16];
    __shared__ __align__(16) float Bs[2][192 * 16];

    const int t    = threadIdx.x;
    const int lane = t & 31;
    const int warp = t >> 5;
    const int g    = lane >> 2;   // group 0..7
    const int q4   = lane & 3;    // 0..3
    const int wm   = warp >> 2;   // 0..1
    const int wn   = warp & 3;    // 0..3
    const int m0   = blockIdx.x * 64;

    // A gmem assignment: thread -> (row = t/4, k-quad u = t%4)
    const int arow = t >> 2;
    const int au   = t & 3;
    const float* aptr = x + (size_t)(m0 + arow) * Cn + au * 4;

    // B gmem assignment: 768 float4 per tile, 3 per thread
    int bk[3], bn[3];
    const float* bp[3];
#pragma unroll
    for (int r = 0; r < 3; ++r) {
        int f  = t + 256 * r;
        int k  = f / 48;
        int n  = (f % 48) * 4;
        bk[r] = k; bn[r] = n;
        const float* W = (n < 64) ? Wq : (n < 128) ? Wk : Wv;
        bp[r] = W + (size_t)k * Hn + (n & 63);
    }

    float acc[2][6][4];
#pragma unroll
    for (int i = 0; i < 2; ++i)
#pragma unroll
        for (int j = 0; j < 6; ++j)
#pragma unroll
            for (int e = 0; e < 4; ++e) acc[i][j][e] = 0.f;

    float4 aR, bR[3];

    // prologue: tile 0
    aR = *(const float4*)aptr;
#pragma unroll
    for (int r = 0; r < 3; ++r) bR[r] = *(const float4*)(bp[r]);
    {
        float av[4] = {aR.x, aR.y, aR.z, aR.w};
#pragma unroll
        for (int e = 0; e < 4; ++e) As[0][swz(arow, e, au)] = f2tf(av[e]);
#pragma unroll
        for (int r = 0; r < 3; ++r) {
            float bv[4] = {bR[r].x, bR[r].y, bR[r].z, bR[r].w};
#pragma unroll
            for (int e = 0; e < 4; ++e)
                Bs[0][swz(bn[r] + e, bk[r] & 3, bk[r] >> 2)] = f2tf(bv[e]);
        }
    }
    __syncthreads();

    for (int it = 0; it < Cn / 16; ++it) {
        const int s = it & 1;
        if (it < Cn / 16 - 1) {
            aR = *(const float4*)(aptr + (it + 1) * 16);
#pragma unroll
            for (int r = 0; r < 3; ++r)
                bR[r] = *(const float4*)(bp[r] + (size_t)(it + 1) * 16 * Hn);
        }

        // A fragments (both k8 steps of the k16 chunk)
        unsigned a[2][2][4];
#pragma unroll
        for (int i = 0; i < 2; ++i) {
            int rA = wm * 32 + 16 * i + g;
            int rB = rA + 8;
            float4 lo = *(const float4*)&As[s][swz(rA, q4, 0)];
            float4 hi = *(const float4*)&As[s][swz(rB, q4, 0)];
            a[i][0][0] = __float_as_uint(lo.x); a[i][0][1] = __float_as_uint(hi.x);
            a[i][0][2] = __float_as_uint(lo.y); a[i][0][3] = __float_as_uint(hi.y);
            a[i][1][0] = __float_as_uint(lo.z); a[i][1][1] = __float_as_uint(hi.z);
            a[i][1][2] = __float_as_uint(lo.w); a[i][1][3] = __float_as_uint(hi.w);
        }
#pragma unroll
        for (int j = 0; j < 6; ++j) {
            int n = wn * 48 + 8 * j + g;
            float4 bv = *(const float4*)&Bs[s][swz(n, q4, 0)];
            unsigned b00 = __float_as_uint(bv.x), b01 = __float_as_uint(bv.y);
            unsigned b10 = __float_as_uint(bv.z), b11 = __float_as_uint(bv.w);
#pragma unroll
            for (int i = 0; i < 2; ++i) {
                mma_tf32(acc[i][j][0], acc[i][j][1], acc[i][j][2], acc[i][j][3],
                         a[i][0][0], a[i][0][1], a[i][0][2], a[i][0][3], b00, b01);
                mma_tf32(acc[i][j][0], acc[i][j][1], acc[i][j][2], acc[i][j][3],
                         a[i][1][0], a[i][1][1], a[i][1][2], a[i][1][3], b10, b11);
            }
        }

        if (it < Cn / 16 - 1) {
            const int d = s ^ 1;
            float av[4] = {aR.x, aR.y, aR.z, aR.w};
#pragma unroll
            for (int e = 0; e < 4; ++e) As[d][swz(arow, e, au)] = f2tf(av[e]);
#pragma unroll
            for (int r = 0; r < 3; ++r) {
                float bv[4] = {bR[r].x, bR[r].y, bR[r].z, bR[r].w};
#pragma unroll
                for (int e = 0; e < 4; ++e)
                    Bs[d][swz(bn[r] + e, bk[r] & 3, bk[r] >> 2)] = f2tf(bv[e]);
            }
        }
        __syncthreads();
    }

    // epilogue: scatter to g_Q (scaled) / g_K / g_V
#pragma unroll
    for (int i = 0; i < 2; ++i) {
        int row = m0 + wm * 32 + 16 * i + g;
#pragma unroll
        for (int j = 0; j < 6; ++j) {
            int nn = wn * 48 + 8 * j;
            float* dst = (nn < 64) ? g_Q : (nn < 128) ? g_K : g_V;
            float sc = (nn < 64) ? 0.125f : 1.0f;
            int col = (nn & 63) + 2 * q4;
            *(float2*)&dst[(size_t)row * Hn + col] =
                make_float2(acc[i][j][0] * sc, acc[i][j][1] * sc);
            *(float2*)&dst[(size_t)(row + 8) * Hn + col] =
                make_float2(acc[i][j][2] * sc, acc[i][j][3] * sc);
        }
    }
}

// ---------------------------------------------------------------------------
// Kernel 2: causal flash attention via tf32 mma.
// Br = Kc = 64, 128 threads = 4 warps, each warp owns 16 full query rows
// (warp S tile 16x64 -> softmax row stats reduce within a quad, 2 shfls).
// Q fragments register-resident; P routed through the freed Q smem buffer
// (warp-local rows -> __syncwarp only). Static smem = 48KB.
// ---------------------------------------------------------------------------
__global__ __launch_bounds__(128, 3)
void attn_mma(float* __restrict__ out)
{
    __shared__ __align__(16) float Ps[64 * 64];  // Q (chunked), then P
    __shared__ __align__(16) float Ks[64 * 64];  // K rows=key, k=embedding
    __shared__ __align__(16) float Vs[64 * 64];  // V^T rows=dim, k=key

    const int t    = threadIdx.x;
    const int lane = t & 31;
    const int warp = t >> 5;
    const int g    = lane >> 2;
    const int q4   = lane & 3;
    const int qt   = 31 - (int)(blockIdx.x >> 3);  // heavy tiles first
    const int b    = blockIdx.x & 7;
    const int q0   = qt * 64;

    // ---- load Q (tf32) into chunked smem ----
    {
        const float* Qg = g_Q + ((size_t)b * Tn + q0) * Hn;
        for (int i4 = t; i4 < 1024; i4 += 128) {
            int row = i4 >> 4, u4 = i4 & 15;
            float4 v = *(const float4*)&Qg[row * Hn + u4 * 4];
            int kc = u4 >> 2, k4 = u4 & 3;
            float* base = &Ps[kc * 1024];
            float av[4] = {v.x, v.y, v.z, v.w};
#pragma unroll
            for (int e = 0; e < 4; ++e) base[swz(row, e, k4)] = f2tf(av[e]);
        }
    }
    __syncthreads();

    const int rA = warp * 16 + g;   // local query row
    const int rB = rA + 8;

    // ---- extract Q a-fragments (8 k-steps) into registers ----
    unsigned qA[8][4];
#pragma unroll
    for (int kc = 0; kc < 4; ++kc) {
        float4 lo = *(const float4*)&Ps[kc * 1024 + swz(rA, q4, 0)];
        float4 hi = *(const float4*)&Ps[kc * 1024 + swz(rB, q4, 0)];
        qA[2*kc][0]   = __float_as_uint(lo.x); qA[2*kc][1]   = __float_as_uint(hi.x);
        qA[2*kc][2]   = __float_as_uint(lo.y); qA[2*kc][3]   = __float_as_uint(hi.y);
        qA[2*kc+1][0] = __float_as_uint(lo.z); qA[2*kc+1][1] = __float_as_uint(hi.z);
        qA[2*kc+1][2] = __float_as_uint(lo.w); qA[2*kc+1][3] = __float_as_uint(hi.w);
    }

    float O[8][4];
#pragma unroll
    for (int j = 0; j < 8; ++j)
#pragma unroll
        for (int e = 0; e < 4; ++e) O[j][e] = 0.f;
    float mA = -1e30f, mB = -1e30f, lA = 0.f, lB = 0.f;

    for (int jt = 0; jt <= qt; ++jt) {
        __syncthreads();   // prior iter's smem reads (K,V,P) complete

        // ---- load K tile (direct) + V tile (transposed) ----
        {
            const float* Kg = g_K + ((size_t)b * Tn + jt * 64) * Hn;
            const float* Vg = g_V + ((size_t)b * Tn + jt * 64) * Hn;
            for (int i4 = t; i4 < 1024; i4 += 128) {
                int row = i4 >> 4, u4 = i4 & 15;
                float4 v = *(const float4*)&Kg[row * Hn + u4 * 4];
                int kc = u4 >> 2, k4 = u4 & 3;
                float* base = &Ks[kc * 1024];
                float av[4] = {v.x, v.y, v.z, v.w};
#pragma unroll
                for (int e = 0; e < 4; ++e) base[swz(row, e, k4)] = f2tf(av[e]);
            }
            for (int i4 = t; i4 < 1024; i4 += 128) {
                int key = i4 >> 4, u4 = i4 & 15;
                float4 v = *(const float4*)&Vg[key * Hn + u4 * 4];
                int kc = key >> 4, c4 = key & 3, k4 = (key >> 2) & 3;
                float* base = &Vs[kc * 1024];
                float av[4] = {v.x, v.y, v.z, v.w};
#pragma unroll
                for (int e = 0; e < 4; ++e) {
                    int d = u4 * 4 + e;
                    base[swz(d, c4, k4)] = f2tf(av[e]);
                }
            }
        }
        __syncthreads();

        // ---- S = Q @ K^T ----
        float S[8][4];
#pragma unroll
        for (int j = 0; j < 8; ++j)
#pragma unroll
            for (int e = 0; e < 4; ++e) S[j][e] = 0.f;

#pragma unroll
        for (int kc = 0; kc < 4; ++kc) {
#pragma unroll
            for (int jb = 0; jb < 8; jb += 4) {
                float4 kf[4];
#pragma unroll
                for (int j = 0; j < 4; ++j) {
                    int n = 8 * (jb + j) + g;
                    kf[j] = *(const float4*)&Ks[kc * 1024 + swz(n, q4, 0)];
                }
#pragma unroll
                for (int j = 0; j < 4; ++j) {
                    int jj = jb + j;
                    mma_tf32(S[jj][0], S[jj][1], S[jj][2], S[jj][3],
                             qA[2*kc][0], qA[2*kc][1], qA[2*kc][2], qA[2*kc][3],
                             __float_as_uint(kf[j].x), __float_as_uint(kf[j].y));
                    mma_tf32(S[jj][0], S[jj][1], S[jj][2], S[jj][3],
                             qA[2*kc+1][0], qA[2*kc+1][1], qA[2*kc+1][2], qA[2*kc+1][3],
                             __float_as_uint(kf[j].z), __float_as_uint(kf[j].w));
                }
            }
        }

        // ---- causal mask on the diagonal tile ----
        if (jt == qt) {
#pragma unroll
            for (int j = 0; j < 8; ++j) {
                int c = 8 * j + 2 * q4;
                if (c     > rA) S[j][0] = -1e30f;
                if (c + 1 > rA) S[j][1] = -1e30f;
                if (c     > rB) S[j][2] = -1e30f;
                if (c + 1 > rB) S[j][3] = -1e30f;
            }
        }

        // ---- online softmax (rows rA, rB; quad reduction) ----
        float mxA = -1e30f, mxB = -1e30f;
#pragma unroll
        for (int j = 0; j < 8; ++j) {
            mxA = fmaxf(mxA, fmaxf(S[j][0], S[j][1]));
            mxB = fmaxf(mxB, fmaxf(S[j][2], S[j][3]));
        }
        mxA = fmaxf(mxA, __shfl_xor_sync(0xffffffffu, mxA, 1));
        mxA = fmaxf(mxA, __shfl_xor_sync(0xffffffffu, mxA, 2));
        mxB = fmaxf(mxB, __shfl_xor_sync(0xffffffffu, mxB, 1));
        mxB = fmaxf(mxB, __shfl_xor_sync(0xffffffffu, mxB, 2));

        float nmA = fmaxf(mA, mxA), nmB = fmaxf(mB, mxB);
        float fA = __expf(mA - nmA), fB = __expf(mB - nmB);
        mA = nmA; mB = nmB;

        float sA = 0.f, sB = 0.f;
#pragma unroll
        for (int j = 0; j < 8; ++j) {
            S[j][0] = __expf(S[j][0] - nmA); sA += S[j][0];
            S[j][1] = __expf(S[j][1] - nmA); sA += S[j][1];
            S[j][2] = __expf(S[j][2] - nmB); sB += S[j][2];
            S[j][3] = __expf(S[j][3] - nmB); sB += S[j][3];
        }
        lA = lA * fA + sA;
        lB = lB * fB + sB;
#pragma unroll
        for (int j = 0; j < 8; ++j) {
            O[j][0] *= fA; O[j][1] *= fA;
            O[j][2] *= fB; O[j][3] *= fB;
        }

        // ---- store P (tf32) into the freed Q buffer; warp-local rows ----
#pragma unroll
        for (int j = 0; j < 8; ++j) {
            int c0 = 8 * j + 2 * q4, c1 = c0 + 1;
            Ps[(c0 >> 4) * 1024 + rA * 16 + (((c0 & 3) ^ (rA & 3)) << 2) + ((c0 >> 2) & 3)] = f2tf(S[j][0]);
            Ps[(c1 >> 4) * 1024 + rA * 16 + (((c1 & 3) ^ (rA & 3)) << 2) + ((c1 >> 2) & 3)] = f2tf(S[j][1]);
            Ps[(c0 >> 4) * 1024 + rB * 16 + (((c0 & 3) ^ (rB & 3)) << 2) + ((c0 >> 2) & 3)] = f2tf(S[j][2]);
            Ps[(c1 >> 4) * 1024 + rB * 16 + (((c1 & 3) ^ (rB & 3)) << 2) + ((c1 >> 2) & 3)] = f2tf(S[j][3]);
        }
        __syncwarp();

        // ---- O += P @ V ----
#pragma unroll
        for (int kc = 0; kc < 4; ++kc) {
            float4 pLo = *(const float4*)&Ps[kc * 1024 + swz(rA, q4, 0)];
            float4 pHi = *(const float4*)&Ps[kc * 1024 + swz(rB, q4, 0)];
            unsigned a00 = __float_as_uint(pLo.x), a01 = __float_as_uint(pHi.x);
            unsigned a02 = __float_as_uint(pLo.y), a03 = __float_as_uint(pHi.y);
            unsigned a10 = __float_as_uint(pLo.z), a11 = __float_as_uint(pHi.z);
            unsigned a12 = __float_as_uint(pLo.w), a13 = __float_as_uint(pHi.w);
#pragma unroll
            for (int jb = 0; jb < 8; jb += 4) {
                float4 vf[4];
#pragma unroll
                for (int j = 0; j < 4; ++j) {
                    int n = 8 * (jb + j) + g;
                    vf[j] = *(const float4*)&Vs[kc * 1024 + swz(n, q4, 0)];
                }
#pragma unroll
                for (int j = 0; j < 4; ++j) {
                    int jj = jb + j;
                    mma_tf32(O[jj][0], O[jj][1], O[jj][2], O[jj][3],
                             a00, a01, a02, a03,
                             __float_as_uint(vf[j].x), __float_as_uint(vf[j].y));
                    mma_tf32(O[jj][0], O[jj][1], O[jj][2], O[jj][3],
                             a10, a11, a12, a13,
                             __float_as_uint(vf[j].z), __float_as_uint(vf[j].w));
                }
            }
        }
    }

    // ---- finalize ----
    lA += __shfl_xor_sync(0xffffffffu, lA, 1);
    lA += __shfl_xor_sync(0xffffffffu, lA, 2);
    lB += __shfl_xor_sync(0xffffffffu, lB, 1);
    lB += __shfl_xor_sync(0xffffffffu, lB, 2);
    float invA = 1.f / lA, invB = 1.f / lB;

    size_t rowAg = (size_t)b * Tn + q0 + rA;
    size_t rowBg = rowAg + 8;
#pragma unroll
    for (int j = 0; j < 8; ++j) {
        int c = 8 * j + 2 * q4;
        *(float2*)&out[rowAg * Hn + c] = make_float2(O[j][0] * invA, O[j][1] * invA);
        *(float2*)&out[rowBg * Hn + c] = make_float2(O[j][2] * invB, O[j][3] * invB);
    }
}

// ---------------------------------------------------------------------------
extern "C" void kernel_launch(void* const* d_in, const int* in_sizes, int n_in,
                              void* d_out, int out_size)
{
    (void)in_sizes; (void)n_in; (void)out_size;
    const float* x  = (const float*)d_in[0];
    const float* Wq = (const float*)d_in[1];
    const float* Wk = (const float*)d_in[2];
    const float* Wv = (const float*)d_in[3];
    float* out = (float*)d_out;

    qkv_mma<<<Mn / 64, 256>>>(x, Wq, Wk, Wv);
    attn_mma<<<Bn * (Tn / 64), 128>>>(out);
}

// round 13
// speedup vs baseline: 1.0602x; 1.0112x over previous
#include <cuda_runtime.h>

// Problem constants
#define Bn 8
#define Tn 2048
#define Cn 1024
#define Hn 64
#define Mn (Bn * Tn)   // 16384 rows

// Scratch for Q, K, V projections (device globals: no runtime allocation)
__device__ float g_Q[(size_t)Mn * Hn];
__device__ float g_K[(size_t)Mn * Hn];
__device__ float g_V[(size_t)Mn * Hn];

// ---------------------------------------------------------------------------
// Helpers
// ---------------------------------------------------------------------------
__device__ __forceinline__ float f2tf(float f) {
    unsigned u;
    asm("cvt.rna.tf32.f32 %0, %1;" : "=r"(u) : "f"(f));
    return __uint_as_float(u);
}

__device__ __forceinline__ void mma_tf32(float& d0, float& d1, float& d2, float& d3,
                                         unsigned a0, unsigned a1, unsigned a2, unsigned a3,
                                         unsigned b0, unsigned b1)
{
    asm volatile(
        "mma.sync.aligned.m16n8k8.row.col.f32.tf32.tf32.f32 "
        "{%0,%1,%2,%3}, {%4,%5,%6,%7}, {%8,%9}, {%0,%1,%2,%3};\n"
        : "+f"(d0), "+f"(d1), "+f"(d2), "+f"(d3)
        : "r"(a0), "r"(a1), "r"(a2), "r"(a3), "r"(b0), "r"(b1));
}

// k16-chunk swizzled smem index: tile row `row`, k = c4 + 4*k4 within chunk.
// Layout row*16 + ((c4 ^ (row&3))<<2) + k4  -> LDS.128 at (row, c4) is
// conflict-free across the 8-thread phases of a warp fragment load.
__device__ __forceinline__ int swz(int row, int c4, int k4) {
    return row * 16 + (((c4 ^ (row & 3))) << 2) + k4;
}

// ---------------------------------------------------------------------------
// Kernel 1: fused QKV projection via tf32 mma.
// C[16384 x 192] = x[16384 x 1024] @ [Wq|Wk|Wv], Q scaled by 1/8.
// BM=64, BN=192, BK=16, 256 threads = 8 warps as 2(m) x 4(n), warp tile 32x48.
// Double-buffered smem, tf32 conversion at STS.
// ---------------------------------------------------------------------------
__global__ __launch_bounds__(256, 2)
void qkv_mma(const float* __restrict__ x, const float* __restrict__ Wq,
             const float* __restrict__ Wk, const float* __restrict__ Wv)
{
    __shared__ __align__(16) float As[2][64 * 16];
    __shared__ __align__(16) float Bs[2][192 * 16];

    const int t    = threadIdx.x;
    const int lane = t & 31;
    const int warp = t >> 5;
    const int g    = lane >> 2;   // group 0..7
    const int q4   = lane & 3;    // 0..3
    const int wm   = warp >> 2;   // 0..1
    const int wn   = warp & 3;    // 0..3
    const int m0   = blockIdx.x * 64;

    // A gmem assignment: thread -> (row = t/4, k-quad u = t%4)
    const int arow = t >> 2;
    const int au   = t & 3;
    const float* aptr = x + (size_t)(m0 + arow) * Cn + au * 4;

    // B gmem assignment: 768 float4 per tile, 3 per thread
    int bk[3], bn[3];
    const float* bp[3];
#pragma unroll
    for (int r = 0; r < 3; ++r) {
        int f  = t + 256 * r;
        int k  = f / 48;
        int n  = (f % 48) * 4;
        bk[r] = k; bn[r] = n;
        const float* W = (n < 64) ? Wq : (n < 128) ? Wk : Wv;
        bp[r] = W + (size_t)k * Hn + (n & 63);
    }

    float acc[2][6][4];
#pragma unroll
    for (int i = 0; i < 2; ++i)
#pragma unroll
        for (int j = 0; j < 6; ++j)
#pragma unroll
            for (int e = 0; e < 4; ++e) acc[i][j][e] = 0.f;

    float4 aR, bR[3];

    // prologue: tile 0
    aR = *(const float4*)aptr;
#pragma unroll
    for (int r = 0; r < 3; ++r) bR[r] = *(const float4*)(bp[r]);
    {
        float av[4] = {aR.x, aR.y, aR.z, aR.w};
#pragma unroll
        for (int e = 0; e < 4; ++e) As[0][swz(arow, e, au)] = f2tf(av[e]);
#pragma unroll
        for (int r = 0; r < 3; ++r) {
            float bv[4] = {bR[r].x, bR[r].y, bR[r].z, bR[r].w};
#pragma unroll
            for (int e = 0; e < 4; ++e)
                Bs[0][swz(bn[r] + e, bk[r] & 3, bk[r] >> 2)] = f2tf(bv[e]);
        }
    }
    __syncthreads();

    for (int it = 0; it < Cn / 16; ++it) {
        const int s = it & 1;
        if (it < Cn / 16 - 1) {
            aR = *(const float4*)(aptr + (it + 1) * 16);
#pragma unroll
            for (int r = 0; r < 3; ++r)
                bR[r] = *(const float4*)(bp[r] + (size_t)(it + 1) * 16 * Hn);
        }

        // A fragments (both k8 steps of the k16 chunk)
        unsigned a[2][2][4];
#pragma unroll
        for (int i = 0; i < 2; ++i) {
            int rA = wm * 32 + 16 * i + g;
            int rB = rA + 8;
            float4 lo = *(const float4*)&As[s][swz(rA, q4, 0)];
            float4 hi = *(const float4*)&As[s][swz(rB, q4, 0)];
            a[i][0][0] = __float_as_uint(lo.x); a[i][0][1] = __float_as_uint(hi.x);
            a[i][0][2] = __float_as_uint(lo.y); a[i][0][3] = __float_as_uint(hi.y);
            a[i][1][0] = __float_as_uint(lo.z); a[i][1][1] = __float_as_uint(hi.z);
            a[i][1][2] = __float_as_uint(lo.w); a[i][1][3] = __float_as_uint(hi.w);
        }
#pragma unroll
        for (int j = 0; j < 6; ++j) {
            int n = wn * 48 + 8 * j + g;
            float4 bv = *(const float4*)&Bs[s][swz(n, q4, 0)];
            unsigned b00 = __float_as_uint(bv.x), b01 = __float_as_uint(bv.y);
            unsigned b10 = __float_as_uint(bv.z), b11 = __float_as_uint(bv.w);
#pragma unroll
            for (int i = 0; i < 2; ++i) {
                mma_tf32(acc[i][j][0], acc[i][j][1], acc[i][j][2], acc[i][j][3],
                         a[i][0][0], a[i][0][1], a[i][0][2], a[i][0][3], b00, b01);
                mma_tf32(acc[i][j][0], acc[i][j][1], acc[i][j][2], acc[i][j][3],
                         a[i][1][0], a[i][1][1], a[i][1][2], a[i][1][3], b10, b11);
            }
        }

        if (it < Cn / 16 - 1) {
            const int d = s ^ 1;
            float av[4] = {aR.x, aR.y, aR.z, aR.w};
#pragma unroll
            for (int e = 0; e < 4; ++e) As[d][swz(arow, e, au)] = f2tf(av[e]);
#pragma unroll
            for (int r = 0; r < 3; ++r) {
                float bv[4] = {bR[r].x, bR[r].y, bR[r].z, bR[r].w};
#pragma unroll
                for (int e = 0; e < 4; ++e)
                    Bs[d][swz(bn[r] + e, bk[r] & 3, bk[r] >> 2)] = f2tf(bv[e]);
            }
        }
        __syncthreads();
    }

    // epilogue: scatter to g_Q (scaled) / g_K / g_V
#pragma unroll
    for (int i = 0; i < 2; ++i) {
        int row = m0 + wm * 32 + 16 * i + g;
#pragma unroll
        for (int j = 0; j < 6; ++j) {
            int nn = wn * 48 + 8 * j;
            float* dst = (nn < 64) ? g_Q : (nn < 128) ? g_K : g_V;
            float sc = (nn < 64) ? 0.125f : 1.0f;
            int col = (nn & 63) + 2 * q4;
            *(float2*)&dst[(size_t)row * Hn + col] =
                make_float2(acc[i][j][0] * sc, acc[i][j][1] * sc);
            *(float2*)&dst[(size_t)(row + 8) * Hn + col] =
                make_float2(acc[i][j][2] * sc, acc[i][j][3] * sc);
        }
    }
}

// ---------------------------------------------------------------------------
// Kernel 2: causal flash attention via tf32 mma.
// Br = Kc = 64, 128 threads = 4 warps, each warp owns 16 full query rows
// (warp S tile 16x64 -> softmax row stats reduce within a quad, 2 shfls).
// Q fragments register-resident; P routed through the freed Q smem buffer
// (warp-local rows -> __syncwarp only). Static smem = 48KB.
// ---------------------------------------------------------------------------
__global__ __launch_bounds__(128, 3)
void attn_mma(float* __restrict__ out)
{
    __shared__ __align__(16) float Ps[64 * 64];  // Q (chunked), then P
    __shared__ __align__(16) float Ks[64 * 64];  // K rows=key, k=embedding
    __shared__ __align__(16) float Vs[64 * 64];  // V^T rows=dim, k=key

    const int t    = threadIdx.x;
    const int lane = t & 31;
    const int warp = t >> 5;
    const int g    = lane >> 2;
    const int q4   = lane & 3;
    const int qt   = 31 - (int)(blockIdx.x >> 3);  // heavy tiles first
    const int b    = blockIdx.x & 7;
    const int q0   = qt * 64;

    // ---- load Q (tf32) into chunked smem ----
    {
        const float* Qg = g_Q + ((size_t)b * Tn + q0) * Hn;
        for (int i4 = t; i4 < 1024; i4 += 128) {
            int row = i4 >> 4, u4 = i4 & 15;
            float4 v = *(const float4*)&Qg[row * Hn + u4 * 4];
            int kc = u4 >> 2, k4 = u4 & 3;
            float* base = &Ps[kc * 1024];
            float av[4] = {v.x, v.y, v.z, v.w};
#pragma unroll
            for (int e = 0; e < 4; ++e) base[swz(row, e, k4)] = f2tf(av[e]);
        }
    }
    __syncthreads();

    const int rA = warp * 16 + g;   // local query row
    const int rB = rA + 8;

    // ---- extract Q a-fragments (8 k-steps) into registers ----
    unsigned qA[8][4];
#pragma unroll
    for (int kc = 0; kc < 4; ++kc) {
        float4 lo = *(const float4*)&Ps[kc * 1024 + swz(rA, q4, 0)];
        float4 hi = *(const float4*)&Ps[kc * 1024 + swz(rB, q4, 0)];
        qA[2*kc][0]   = __float_as_uint(lo.x); qA[2*kc][1]   = __float_as_uint(hi.x);
        qA[2*kc][2]   = __float_as_uint(lo.y); qA[2*kc][3]   = __float_as_uint(hi.y);
        qA[2*kc+1][0] = __float_as_uint(lo.z); qA[2*kc+1][1] = __float_as_uint(hi.z);
        qA[2*kc+1][2] = __float_as_uint(lo.w); qA[2*kc+1][3] = __float_as_uint(hi.w);
    }

    float O[8][4];
#pragma unroll
    for (int j = 0; j < 8; ++j)
#pragma unroll
        for (int e = 0; e < 4; ++e) O[j][e] = 0.f;
    float mA = -1e30f, mB = -1e30f, lA = 0.f, lB = 0.f;

    for (int jt = 0; jt <= qt; ++jt) {
        __syncthreads();   // prior iter's smem reads (K,V,P) complete

        // ---- load K tile (direct) + V tile (transposed) ----
        {
            const float* Kg = g_K + ((size_t)b * Tn + jt * 64) * Hn;
            const float* Vg = g_V + ((size_t)b * Tn + jt * 64) * Hn;
            for (int i4 = t; i4 < 1024; i4 += 128) {
                int row = i4 >> 4, u4 = i4 & 15;
                float4 v = *(const float4*)&Kg[row * Hn + u4 * 4];
                int kc = u4 >> 2, k4 = u4 & 3;
                float* base = &Ks[kc * 1024];
                float av[4] = {v.x, v.y, v.z, v.w};
#pragma unroll
                for (int e = 0; e < 4; ++e) base[swz(row, e, k4)] = f2tf(av[e]);
            }
            for (int i4 = t; i4 < 1024; i4 += 128) {
                int key = i4 >> 4, u4 = i4 & 15;
                float4 v = *(const float4*)&Vg[key * Hn + u4 * 4];
                int kc = key >> 4, c4 = key & 3, k4 = (key >> 2) & 3;
                float* base = &Vs[kc * 1024];
                float av[4] = {v.x, v.y, v.z, v.w};
#pragma unroll
                for (int e = 0; e < 4; ++e) {
                    int d = u4 * 4 + e;
                    base[swz(d, c4, k4)] = f2tf(av[e]);
                }
            }
        }
        __syncthreads();

        // ---- S = Q @ K^T ----
        float S[8][4];
#pragma unroll
        for (int j = 0; j < 8; ++j)
#pragma unroll
            for (int e = 0; e < 4; ++e) S[j][e] = 0.f;

#pragma unroll
        for (int kc = 0; kc < 4; ++kc) {
#pragma unroll
            for (int jb = 0; jb < 8; jb += 4) {
                float4 kf[4];
#pragma unroll
                for (int j = 0; j < 4; ++j) {
                    int n = 8 * (jb + j) + g;
                    kf[j] = *(const float4*)&Ks[kc * 1024 + swz(n, q4, 0)];
                }
#pragma unroll
                for (int j = 0; j < 4; ++j) {
                    int jj = jb + j;
                    mma_tf32(S[jj][0], S[jj][1], S[jj][2], S[jj][3],
                             qA[2*kc][0], qA[2*kc][1], qA[2*kc][2], qA[2*kc][3],
                             __float_as_uint(kf[j].x), __float_as_uint(kf[j].y));
                    mma_tf32(S[jj][0], S[jj][1], S[jj][2], S[jj][3],
                             qA[2*kc+1][0], qA[2*kc+1][1], qA[2*kc+1][2], qA[2*kc+1][3],
                             __float_as_uint(kf[j].z), __float_as_uint(kf[j].w));
                }
            }
        }

        // ---- causal mask on the diagonal tile ----
        if (jt == qt) {
#pragma unroll
            for (int j = 0; j < 8; ++j) {
                int c = 8 * j + 2 * q4;
                if (c     > rA) S[j][0] = -1e30f;
                if (c + 1 > rA) S[j][1] = -1e30f;
                if (c     > rB) S[j][2] = -1e30f;
                if (c + 1 > rB) S[j][3] = -1e30f;
            }
        }

        // ---- online softmax (rows rA, rB; quad reduction) ----
        float mxA = -1e30f, mxB = -1e30f;
#pragma unroll
        for (int j = 0; j < 8; ++j) {
            mxA = fmaxf(mxA, fmaxf(S[j][0], S[j][1]));
            mxB = fmaxf(mxB, fmaxf(S[j][2], S[j][3]));
        }
        mxA = fmaxf(mxA, __shfl_xor_sync(0xffffffffu, mxA, 1));
        mxA = fmaxf(mxA, __shfl_xor_sync(0xffffffffu, mxA, 2));
        mxB = fmaxf(mxB, __shfl_xor_sync(0xffffffffu, mxB, 1));
        mxB = fmaxf(mxB, __shfl_xor_sync(0xffffffffu, mxB, 2));

        float nmA = fmaxf(mA, mxA), nmB = fmaxf(mB, mxB);
        float fA = __expf(mA - nmA), fB = __expf(mB - nmB);
        mA = nmA; mB = nmB;

        float sA = 0.f, sB = 0.f;
#pragma unroll
        for (int j = 0; j < 8; ++j) {
            S[j][0] = __expf(S[j][0] - nmA); sA += S[j][0];
            S[j][1] = __expf(S[j][1] - nmA); sA += S[j][1];
            S[j][2] = __expf(S[j][2] - nmB); sB += S[j][2];
            S[j][3] = __expf(S[j][3] - nmB); sB += S[j][3];
        }
        lA = lA * fA + sA;
        lB = lB * fB + sB;
#pragma unroll
        for (int j = 0; j < 8; ++j) {
            O[j][0] *= fA; O[j][1] *= fA;
            O[j][2] *= fB; O[j][3] *= fB;
        }

        // ---- store P (tf32) into the freed Q buffer; warp-local rows ----
#pragma unroll
        for (int j = 0; j < 8; ++j) {
            int c0 = 8 * j + 2 * q4, c1 = c0 + 1;
            Ps[(c0 >> 4) * 1024 + rA * 16 + (((c0 & 3) ^ (rA & 3)) << 2) + ((c0 >> 2) & 3)] = f2tf(S[j][0]);
            Ps[(c1 >> 4) * 1024 + rA * 16 + (((c1 & 3) ^ (rA & 3)) << 2) + ((c1 >> 2) & 3)] = f2tf(S[j][1]);
            Ps[(c0 >> 4) * 1024 + rB * 16 + (((c0 & 3) ^ (rB & 3)) << 2) + ((c0 >> 2) & 3)] = f2tf(S[j][2]);
            Ps[(c1 >> 4) * 1024 + rB * 16 + (((c1 & 3) ^ (rB & 3)) << 2) + ((c1 >> 2) & 3)] = f2tf(S[j][3]);
        }
        __syncwarp();

        // ---- O += P @ V ----
#pragma unroll
        for (int kc = 0; kc < 4; ++kc) {
            float4 pLo = *(const float4*)&Ps[kc * 1024 + swz(rA, q4, 0)];
            float4 pHi = *(const float4*)&Ps[kc * 1024 + swz(rB, q4, 0)];
            unsigned a00 = __float_as_uint(pLo.x), a01 = __float_as_uint(pHi.x);
            unsigned a02 = __float_as_uint(pLo.y), a03 = __float_as_uint(pHi.y);
            unsigned a10 = __float_as_uint(pLo.z), a11 = __float_as_uint(pHi.z);
            unsigned a12 = __float_as_uint(pLo.w), a13 = __float_as_uint(pHi.w);
#pragma unroll
            for (int jb = 0; jb < 8; jb += 4) {
                float4 vf[4];
#pragma unroll
                for (int j = 0; j < 4; ++j) {
                    int n = 8 * (jb + j) + g;
                    vf[j] = *(const float4*)&Vs[kc * 1024 + swz(n, q4, 0)];
                }
#pragma unroll
                for (int j = 0; j < 4; ++j) {
                    int jj = jb + j;
                    mma_tf32(O[jj][0], O[jj][1], O[jj][2], O[jj][3],
                             a00, a01, a02, a03,
                             __float_as_uint(vf[j].x), __float_as_uint(vf[j].y));
                    mma_tf32(O[jj][0], O[jj][1], O[jj][2], O[jj][3],
                             a10, a11, a12, a13,
                             __float_as_uint(vf[j].z), __float_as_uint(vf[j].w));
                }
            }
        }
    }

    // ---- finalize ----
    lA += __shfl_xor_sync(0xffffffffu, lA, 1);
    lA += __shfl_xor_sync(0xffffffffu, lA, 2);
    lB += __shfl_xor_sync(0xffffffffu, lB, 1);
    lB += __shfl_xor_sync(0xffffffffu, lB, 2);
    float invA = 1.f / lA, invB = 1.f / lB;

    size_t rowAg = (size_t)b * Tn + q0 + rA;
    size_t rowBg = rowAg + 8;
#pragma unroll
    for (int j = 0; j < 8; ++j) {
        int c = 8 * j + 2 * q4;
        *(float2*)&out[rowAg * Hn + c] = make_float2(O[j][0] * invA, O[j][1] * invA);
        *(float2*)&out[rowBg * Hn + c] = make_float2(O[j][2] * invB, O[j][3] * invB);
    }
}

// ---------------------------------------------------------------------------
extern "C" void kernel_launch(void* const* d_in, const int* in_sizes, int n_in,
                              void* d_out, int out_size)
{
    (void)in_sizes; (void)n_in; (void)out_size;
    const float* x  = (const float*)d_in[0];
    const float* Wq = (const float*)d_in[1];
    const float* Wk = (const float*)d_in[2];
    const float* Wv = (const float*)d_in[3];
    float* out = (float*)d_out;

    qkv_mma<<<Mn / 64, 256>>>(x, Wq, Wk, Wv);
    attn_mma<<<Bn * (Tn / 64), 128>>>(out);
}

// round 14
// speedup vs baseline: 1.0603x; 1.0001x over previous
#include <cuda_runtime.h>

// Problem constants
#define Bn 8
#define Tn 2048
#define Cn 1024
#define Hn 64
#define Mn (Bn * Tn)   // 16384 rows

// Scratch for Q, K, V projections (device globals: no runtime allocation)
__device__ float g_Q[(size_t)Mn * Hn];
__device__ float g_K[(size_t)Mn * Hn];
__device__ float g_V[(size_t)Mn * Hn];

// ---------------------------------------------------------------------------
// Helpers
// ---------------------------------------------------------------------------
__device__ __forceinline__ float f2tf(float f) {
    unsigned u;
    asm("cvt.rna.tf32.f32 %0, %1;" : "=r"(u) : "f"(f));
    return __uint_as_float(u);
}

__device__ __forceinline__ void mma_tf32(float& d0, float& d1, float& d2, float& d3,
                                         unsigned a0, unsigned a1, unsigned a2, unsigned a3,
                                         unsigned b0, unsigned b1)
{
    asm volatile(
        "mma.sync.aligned.m16n8k8.row.col.f32.tf32.tf32.f32 "
        "{%0,%1,%2,%3}, {%4,%5,%6,%7}, {%8,%9}, {%0,%1,%2,%3};\n"
        : "+f"(d0), "+f"(d1), "+f"(d2), "+f"(d3)
        : "r"(a0), "r"(a1), "r"(a2), "r"(a3), "r"(b0), "r"(b1));
}

// k16-chunk swizzled smem index: tile row `row`, k = c4 + 4*k4 within chunk.
// Layout row*16 + ((c4 ^ (row&3))<<2) + k4  -> LDS.128 at (row, c4) is
// conflict-free across the 8-thread phases of a warp fragment load.
__device__ __forceinline__ int swz(int row, int c4, int k4) {
    return row * 16 + (((c4 ^ (row & 3))) << 2) + k4;
}

// ---------------------------------------------------------------------------
// Kernel 1: fused QKV projection via tf32 mma.
// C[16384 x 192] = x[16384 x 1024] @ [Wq|Wk|Wv], Q scaled by 1/8.
// BM=64, BN=192, BK=16, 256 threads = 8 warps as 2(m) x 4(n), warp tile 32x48.
// Double-buffered smem, tf32 conversion at STS.
// ---------------------------------------------------------------------------
__global__ __launch_bounds__(256, 2)
void qkv_mma(const float* __restrict__ x, const float* __restrict__ Wq,
             const float* __restrict__ Wk, const float* __restrict__ Wv)
{
    __shared__ __align__(16) float As[2][64 * 16];
    __shared__ __align__(16) float Bs[2][192 * 16];

    const int t    = threadIdx.x;
    const int lane = t & 31;
    const int warp = t >> 5;
    const int g    = lane >> 2;   // group 0..7
    const int q4   = lane & 3;    // 0..3
    const int wm   = warp >> 2;   // 0..1
    const int wn   = warp & 3;    // 0..3
    const int m0   = blockIdx.x * 64;

    // A gmem assignment: thread -> (row = t/4, k-quad u = t%4)
    const int arow = t >> 2;
    const int au   = t & 3;
    const float* aptr = x + (size_t)(m0 + arow) * Cn + au * 4;

    // B gmem assignment: 768 float4 per tile, 3 per thread
    int bk[3], bn[3];
    const float* bp[3];
#pragma unroll
    for (int r = 0; r < 3; ++r) {
        int f  = t + 256 * r;
        int k  = f / 48;
        int n  = (f % 48) * 4;
        bk[r] = k; bn[r] = n;
        const float* W = (n < 64) ? Wq : (n < 128) ? Wk : Wv;
        bp[r] = W + (size_t)k * Hn + (n & 63);
    }

    float acc[2][6][4];
#pragma unroll
    for (int i = 0; i < 2; ++i)
#pragma unroll
        for (int j = 0; j < 6; ++j)
#pragma unroll
            for (int e = 0; e < 4; ++e) acc[i][j][e] = 0.f;

    float4 aR, bR[3];

    // prologue: tile 0
    aR = *(const float4*)aptr;
#pragma unroll
    for (int r = 0; r < 3; ++r) bR[r] = *(const float4*)(bp[r]);
    {
        float av[4] = {aR.x, aR.y, aR.z, aR.w};
#pragma unroll
        for (int e = 0; e < 4; ++e) As[0][swz(arow, e, au)] = f2tf(av[e]);
#pragma unroll
        for (int r = 0; r < 3; ++r) {
            float bv[4] = {bR[r].x, bR[r].y, bR[r].z, bR[r].w};
#pragma unroll
            for (int e = 0; e < 4; ++e)
                Bs[0][swz(bn[r] + e, bk[r] & 3, bk[r] >> 2)] = f2tf(bv[e]);
        }
    }
    __syncthreads();

    for (int it = 0; it < Cn / 16; ++it) {
        const int s = it & 1;
        if (it < Cn / 16 - 1) {
            aR = *(const float4*)(aptr + (it + 1) * 16);
#pragma unroll
            for (int r = 0; r < 3; ++r)
                bR[r] = *(const float4*)(bp[r] + (size_t)(it + 1) * 16 * Hn);
        }

        // A fragments (both k8 steps of the k16 chunk)
        unsigned a[2][2][4];
#pragma unroll
        for (int i = 0; i < 2; ++i) {
            int rA = wm * 32 + 16 * i + g;
            int rB = rA + 8;
            float4 lo = *(const float4*)&As[s][swz(rA, q4, 0)];
            float4 hi = *(const float4*)&As[s][swz(rB, q4, 0)];
            a[i][0][0] = __float_as_uint(lo.x); a[i][0][1] = __float_as_uint(hi.x);
            a[i][0][2] = __float_as_uint(lo.y); a[i][0][3] = __float_as_uint(hi.y);
            a[i][1][0] = __float_as_uint(lo.z); a[i][1][1] = __float_as_uint(hi.z);
            a[i][1][2] = __float_as_uint(lo.w); a[i][1][3] = __float_as_uint(hi.w);
        }
#pragma unroll
        for (int j = 0; j < 6; ++j) {
            int n = wn * 48 + 8 * j + g;
            float4 bv = *(const float4*)&Bs[s][swz(n, q4, 0)];
            unsigned b00 = __float_as_uint(bv.x), b01 = __float_as_uint(bv.y);
            unsigned b10 = __float_as_uint(bv.z), b11 = __float_as_uint(bv.w);
#pragma unroll
            for (int i = 0; i < 2; ++i) {
                mma_tf32(acc[i][j][0], acc[i][j][1], acc[i][j][2], acc[i][j][3],
                         a[i][0][0], a[i][0][1], a[i][0][2], a[i][0][3], b00, b01);
                mma_tf32(acc[i][j][0], acc[i][j][1], acc[i][j][2], acc[i][j][3],
                         a[i][1][0], a[i][1][1], a[i][1][2], a[i][1][3], b10, b11);
            }
        }

        if (it < Cn / 16 - 1) {
            const int d = s ^ 1;
            float av[4] = {aR.x, aR.y, aR.z, aR.w};
#pragma unroll
            for (int e = 0; e < 4; ++e) As[d][swz(arow, e, au)] = f2tf(av[e]);
#pragma unroll
            for (int r = 0; r < 3; ++r) {
                float bv[4] = {bR[r].x, bR[r].y, bR[r].z, bR[r].w};
#pragma unroll
                for (int e = 0; e < 4; ++e)
                    Bs[d][swz(bn[r] + e, bk[r] & 3, bk[r] >> 2)] = f2tf(bv[e]);
            }
        }
        __syncthreads();
    }

    // epilogue: scatter to g_Q (scaled) / g_K / g_V
#pragma unroll
    for (int i = 0; i < 2; ++i) {
        int row = m0 + wm * 32 + 16 * i + g;
#pragma unroll
        for (int j = 0; j < 6; ++j) {
            int nn = wn * 48 + 8 * j;
            float* dst = (nn < 64) ? g_Q : (nn < 128) ? g_K : g_V;
            float sc = (nn < 64) ? 0.125f : 1.0f;
            int col = (nn & 63) + 2 * q4;
            *(float2*)&dst[(size_t)row * Hn + col] =
                make_float2(acc[i][j][0] * sc, acc[i][j][1] * sc);
            *(float2*)&dst[(size_t)(row + 8) * Hn + col] =
                make_float2(acc[i][j][2] * sc, acc[i][j][3] * sc);
        }
    }
}

// ---------------------------------------------------------------------------
// Kernel 2: causal flash attention via tf32 mma.
// Br = Kc = 64, 128 threads = 4 warps, each warp owns 16 full query rows
// (warp S tile 16x64 -> softmax row stats reduce within a quad, 2 shfls).
// Q fragments register-resident; P routed through the freed Q smem buffer
// (warp-local rows -> __syncwarp only). Static smem = 48KB.
// ---------------------------------------------------------------------------
__global__ __launch_bounds__(128, 3)
void attn_mma(float* __restrict__ out)
{
    __shared__ __align__(16) float Ps[64 * 64];  // Q (chunked), then P
    __shared__ __align__(16) float Ks[64 * 64];  // K rows=key, k=embedding
    __shared__ __align__(16) float Vs[64 * 64];  // V^T rows=dim, k=key

    const int t    = threadIdx.x;
    const int lane = t & 31;
    const int warp = t >> 5;
    const int g    = lane >> 2;
    const int q4   = lane & 3;
    const int qt   = 31 - (int)(blockIdx.x >> 3);  // heavy tiles first
    const int b    = blockIdx.x & 7;
    const int q0   = qt * 64;

    // ---- load Q (tf32) into chunked smem ----
    {
        const float* Qg = g_Q + ((size_t)b * Tn + q0) * Hn;
        for (int i4 = t; i4 < 1024; i4 += 128) {
            int row = i4 >> 4, u4 = i4 & 15;
            float4 v = *(const float4*)&Qg[row * Hn + u4 * 4];
            int kc = u4 >> 2, k4 = u4 & 3;
            float* base = &Ps[kc * 1024];
            float av[4] = {v.x, v.y, v.z, v.w};
#pragma unroll
            for (int e = 0; e < 4; ++e) base[swz(row, e, k4)] = f2tf(av[e]);
        }
    }
    __syncthreads();

    const int rA = warp * 16 + g;   // local query row
    const int rB = rA + 8;

    // ---- extract Q a-fragments (8 k-steps) into registers ----
    unsigned qA[8][4];
#pragma unroll
    for (int kc = 0; kc < 4; ++kc) {
        float4 lo = *(const float4*)&Ps[kc * 1024 + swz(rA, q4, 0)];
        float4 hi = *(const float4*)&Ps[kc * 1024 + swz(rB, q4, 0)];
        qA[2*kc][0]   = __float_as_uint(lo.x); qA[2*kc][1]   = __float_as_uint(hi.x);
        qA[2*kc][2]   = __float_as_uint(lo.y); qA[2*kc][3]   = __float_as_uint(hi.y);
        qA[2*kc+1][0] = __float_as_uint(lo.z); qA[2*kc+1][1] = __float_as_uint(hi.z);
        qA[2*kc+1][2] = __float_as_uint(lo.w); qA[2*kc+1][3] = __float_as_uint(hi.w);
    }

    float O[8][4];
#pragma unroll
    for (int j = 0; j < 8; ++j)
#pragma unroll
        for (int e = 0; e < 4; ++e) O[j][e] = 0.f;
    float mA = -1e30f, mB = -1e30f, lA = 0.f, lB = 0.f;

    for (int jt = 0; jt <= qt; ++jt) {
        __syncthreads();   // prior iter's smem reads (K,V,P) complete

        // ---- load K tile (direct) + V tile (transposed) ----
        {
            const float* Kg = g_K + ((size_t)b * Tn + jt * 64) * Hn;
            const float* Vg = g_V + ((size_t)b * Tn + jt * 64) * Hn;
            for (int i4 = t; i4 < 1024; i4 += 128) {
                int row = i4 >> 4, u4 = i4 & 15;
                float4 v = *(const float4*)&Kg[row * Hn + u4 * 4];
                int kc = u4 >> 2, k4 = u4 & 3;
                float* base = &Ks[kc * 1024];
                float av[4] = {v.x, v.y, v.z, v.w};
#pragma unroll
                for (int e = 0; e < 4; ++e) base[swz(row, e, k4)] = f2tf(av[e]);
            }
            for (int i4 = t; i4 < 1024; i4 += 128) {
                int key = i4 >> 4, u4 = i4 & 15;
                float4 v = *(const float4*)&Vg[key * Hn + u4 * 4];
                int kc = key >> 4, c4 = key & 3, k4 = (key >> 2) & 3;
                float* base = &Vs[kc * 1024];
                float av[4] = {v.x, v.y, v.z, v.w};
#pragma unroll
                for (int e = 0; e < 4; ++e) {
                    int d = u4 * 4 + e;
                    base[swz(d, c4, k4)] = f2tf(av[e]);
                }
            }
        }
        __syncthreads();

        // ---- S = Q @ K^T ----
        float S[8][4];
#pragma unroll
        for (int j = 0; j < 8; ++j)
#pragma unroll
            for (int e = 0; e < 4; ++e) S[j][e] = 0.f;

#pragma unroll
        for (int kc = 0; kc < 4; ++kc) {
#pragma unroll
            for (int jb = 0; jb < 8; jb += 4) {
                float4 kf[4];
#pragma unroll
                for (int j = 0; j < 4; ++j) {
                    int n = 8 * (jb + j) + g;
                    kf[j] = *(const float4*)&Ks[kc * 1024 + swz(n, q4, 0)];
                }
#pragma unroll
                for (int j = 0; j < 4; ++j) {
                    int jj = jb + j;
                    mma_tf32(S[jj][0], S[jj][1], S[jj][2], S[jj][3],
                             qA[2*kc][0], qA[2*kc][1], qA[2*kc][2], qA[2*kc][3],
                             __float_as_uint(kf[j].x), __float_as_uint(kf[j].y));
                    mma_tf32(S[jj][0], S[jj][1], S[jj][2], S[jj][3],
                             qA[2*kc+1][0], qA[2*kc+1][1], qA[2*kc+1][2], qA[2*kc+1][3],
                             __float_as_uint(kf[j].z), __float_as_uint(kf[j].w));
                }
            }
        }

        // ---- causal mask on the diagonal tile ----
        if (jt == qt) {
#pragma unroll
            for (int j = 0; j < 8; ++j) {
                int c = 8 * j + 2 * q4;
                if (c     > rA) S[j][0] = -1e30f;
                if (c + 1 > rA) S[j][1] = -1e30f;
                if (c     > rB) S[j][2] = -1e30f;
                if (c + 1 > rB) S[j][3] = -1e30f;
            }
        }

        // ---- online softmax (rows rA, rB; quad reduction) ----
        float mxA = -1e30f, mxB = -1e30f;
#pragma unroll
        for (int j = 0; j < 8; ++j) {
            mxA = fmaxf(mxA, fmaxf(S[j][0], S[j][1]));
            mxB = fmaxf(mxB, fmaxf(S[j][2], S[j][3]));
        }
        mxA = fmaxf(mxA, __shfl_xor_sync(0xffffffffu, mxA, 1));
        mxA = fmaxf(mxA, __shfl_xor_sync(0xffffffffu, mxA, 2));
        mxB = fmaxf(mxB, __shfl_xor_sync(0xffffffffu, mxB, 1));
        mxB = fmaxf(mxB, __shfl_xor_sync(0xffffffffu, mxB, 2));

        float nmA = fmaxf(mA, mxA), nmB = fmaxf(mB, mxB);
        float fA = __expf(mA - nmA), fB = __expf(mB - nmB);
        mA = nmA; mB = nmB;

        float sA = 0.f, sB = 0.f;
#pragma unroll
        for (int j = 0; j < 8; ++j) {
            S[j][0] = __expf(S[j][0] - nmA); sA += S[j][0];
            S[j][1] = __expf(S[j][1] - nmA); sA += S[j][1];
            S[j][2] = __expf(S[j][2] - nmB); sB += S[j][2];
            S[j][3] = __expf(S[j][3] - nmB); sB += S[j][3];
        }
        lA = lA * fA + sA;
        lB = lB * fB + sB;
#pragma unroll
        for (int j = 0; j < 8; ++j) {
            O[j][0] *= fA; O[j][1] *= fA;
            O[j][2] *= fB; O[j][3] *= fB;
        }

        // ---- store P (tf32) into the freed Q buffer; warp-local rows ----
#pragma unroll
        for (int j = 0; j < 8; ++j) {
            int c0 = 8 * j + 2 * q4, c1 = c0 + 1;
            Ps[(c0 >> 4) * 1024 + rA * 16 + (((c0 & 3) ^ (rA & 3)) << 2) + ((c0 >> 2) & 3)] = f2tf(S[j][0]);
            Ps[(c1 >> 4) * 1024 + rA * 16 + (((c1 & 3) ^ (rA & 3)) << 2) + ((c1 >> 2) & 3)] = f2tf(S[j][1]);
            Ps[(c0 >> 4) * 1024 + rB * 16 + (((c0 & 3) ^ (rB & 3)) << 2) + ((c0 >> 2) & 3)] = f2tf(S[j][2]);
            Ps[(c1 >> 4) * 1024 + rB * 16 + (((c1 & 3) ^ (rB & 3)) << 2) + ((c1 >> 2) & 3)] = f2tf(S[j][3]);
        }
        __syncwarp();

        // ---- O += P @ V ----
#pragma unroll
        for (int kc = 0; kc < 4; ++kc) {
            float4 pLo = *(const float4*)&Ps[kc * 1024 + swz(rA, q4, 0)];
            float4 pHi = *(const float4*)&Ps[kc * 1024 + swz(rB, q4, 0)];
            unsigned a00 = __float_as_uint(pLo.x), a01 = __float_as_uint(pHi.x);
            unsigned a02 = __float_as_uint(pLo.y), a03 = __float_as_uint(pHi.y);
            unsigned a10 = __float_as_uint(pLo.z), a11 = __float_as_uint(pHi.z);
            unsigned a12 = __float_as_uint(pLo.w), a13 = __float_as_uint(pHi.w);
#pragma unroll
            for (int jb = 0; jb < 8; jb += 4) {
                float4 vf[4];
#pragma unroll
                for (int j = 0; j < 4; ++j) {
                    int n = 8 * (jb + j) + g;
                    vf[j] = *(const float4*)&Vs[kc * 1024 + swz(n, q4, 0)];
                }
#pragma unroll
                for (int j = 0; j < 4; ++j) {
                    int jj = jb + j;
                    mma_tf32(O[jj][0], O[jj][1], O[jj][2], O[jj][3],
                             a00, a01, a02, a03,
                             __float_as_uint(vf[j].x), __float_as_uint(vf[j].y));
                    mma_tf32(O[jj][0], O[jj][1], O[jj][2], O[jj][3],
                             a10, a11, a12, a13,
                             __float_as_uint(vf[j].z), __float_as_uint(vf[j].w));
                }
            }
        }
    }

    // ---- finalize ----
    lA += __shfl_xor_sync(0xffffffffu, lA, 1);
    lA += __shfl_xor_sync(0xffffffffu, lA, 2);
    lB += __shfl_xor_sync(0xffffffffu, lB, 1);
    lB += __shfl_xor_sync(0xffffffffu, lB, 2);
    float invA = 1.f / lA, invB = 1.f / lB;

    size_t rowAg = (size_t)b * Tn + q0 + rA;
    size_t rowBg = rowAg + 8;
#pragma unroll
    for (int j = 0; j < 8; ++j) {
        int c = 8 * j + 2 * q4;
        *(float2*)&out[rowAg * Hn + c] = make_float2(O[j][0] * invA, O[j][1] * invA);
        *(float2*)&out[rowBg * Hn + c] = make_float2(O[j][2] * invB, O[j][3] * invB);
    }
}

// ---------------------------------------------------------------------------
extern "C" void kernel_launch(void* const* d_in, const int* in_sizes, int n_in,
                              void* d_out, int out_size)
{
    (void)in_sizes; (void)n_in; (void)out_size;
    const float* x  = (const float*)d_in[0];
    const float* Wq = (const float*)d_in[1];
    const float* Wk = (const float*)d_in[2];
    const float* Wv = (const float*)d_in[3];
    float* out = (float*)d_out;

    qkv_mma<<<Mn / 64, 256>>>(x, Wq, Wk, Wv);
    attn_mma<<<Bn * (Tn / 64), 128>>>(out);
}